// round 2
// baseline (speedup 1.0000x reference)
#include <cuda_runtime.h>

#define BATCH_ 131072
#define DD 784
#define HID 256
#define MD 16

// Scratch (device globals; no allocation allowed in kernel_launch)
__device__ float g_h [(size_t)BATCH_ * HID];   // relu(x@W1+b1)
__device__ float g_gf[(size_t)BATCH_ * HID];   // h@W2+b2
__device__ float g_xi[(size_t)BATCH_ * MD];    // x@Wp+bp

// ---------------------------------------------------------------------------
// Classic 128x128x8 register-blocked SGEMM: C = op(A[M,K] @ W[K,N] + bias[N])
// 256 threads, each computes an 8x8 tile. RELU applied when template flag set.
// ---------------------------------------------------------------------------
template <int RELU>
__global__ __launch_bounds__(256)
void sgemm128(const float* __restrict__ A, const float* __restrict__ W,
              const float* __restrict__ bias, float* __restrict__ C,
              int M, int N, int K)
{
    __shared__ float As[8][128];
    __shared__ float Bs[8][128];

    const int tid = threadIdx.x;
    const int tx  = tid & 15;        // 0..15 -> 8 output cols each
    const int ty  = tid >> 4;        // 0..15 -> 8 output rows each
    const size_t br = blockIdx.y;    // M / 128
    const size_t bc = blockIdx.x;    // N / 128

    const float* Ab = A + br * 128 * (size_t)K;
    const float* Wb = W + bc * 128;

    float acc[8][8];
#pragma unroll
    for (int i = 0; i < 8; i++)
#pragma unroll
        for (int j = 0; j < 8; j++) acc[i][j] = 0.0f;

    const int arow = tid >> 1;           // 0..127
    const int ac4  = (tid & 1) * 4;      // 0 or 4
    const int brow = tid >> 5;           // 0..7
    const int bc4  = (tid & 31) * 4;     // 0..124

    for (int kt = 0; kt < K; kt += 8) {
        float4 av = *(const float4*)(Ab + (size_t)arow * K + kt + ac4);
        As[ac4 + 0][arow] = av.x;
        As[ac4 + 1][arow] = av.y;
        As[ac4 + 2][arow] = av.z;
        As[ac4 + 3][arow] = av.w;
        float4 bv = *(const float4*)(Wb + (size_t)(kt + brow) * N + bc4);
        *(float4*)&Bs[brow][bc4] = bv;
        __syncthreads();

#pragma unroll
        for (int k = 0; k < 8; k++) {
            float ar[8], bw[8];
#pragma unroll
            for (int i = 0; i < 8; i++) ar[i] = As[k][ty * 8 + i];
#pragma unroll
            for (int j = 0; j < 8; j++) bw[j] = Bs[k][tx * 8 + j];
#pragma unroll
            for (int i = 0; i < 8; i++)
#pragma unroll
                for (int j = 0; j < 8; j++) acc[i][j] += ar[i] * bw[j];
        }
        __syncthreads();
    }

    float bcol[8];
#pragma unroll
    for (int j = 0; j < 8; j++) bcol[j] = bias[bc * 128 + tx * 8 + j];

#pragma unroll
    for (int i = 0; i < 8; i++) {
        const size_t row = br * 128 + ty * 8 + i;
        float* Crow = C + row * (size_t)N + bc * 128 + tx * 8;
        float4 v0, v1;
        float tmp[8];
#pragma unroll
        for (int j = 0; j < 8; j++) {
            float v = acc[i][j] + bcol[j];
            if (RELU) v = v > 0.0f ? v : 0.0f;
            tmp[j] = v;
        }
        v0.x = tmp[0]; v0.y = tmp[1]; v0.z = tmp[2]; v0.w = tmp[3];
        v1.x = tmp[4]; v1.y = tmp[5]; v1.z = tmp[6]; v1.w = tmp[7];
        *(float4*)(Crow + 0) = v0;
        *(float4*)(Crow + 4) = v1;
    }
}

// ---------------------------------------------------------------------------
// xi = x @ Wp + bp   (B x 784 @ 784 x 16). One warp per row.
// ---------------------------------------------------------------------------
__global__ __launch_bounds__(256)
void xi_kernel(const float* __restrict__ x, const float* __restrict__ Wp,
               const float* __restrict__ bp, float* __restrict__ xiout)
{
    const int w = threadIdx.x >> 5, lane = threadIdx.x & 31;
    const size_t row = (size_t)blockIdx.x * 8 + w;
    const float* xr = x + row * DD;

    float acc[MD];
#pragma unroll
    for (int j = 0; j < MD; j++) acc[j] = 0.0f;

    for (int k = lane; k < DD; k += 32) {
        const float xv = xr[k];
        const float* wr = Wp + (size_t)k * MD;
#pragma unroll
        for (int j = 0; j < MD; j++) acc[j] += xv * __ldg(wr + j);
    }
#pragma unroll
    for (int j = 0; j < MD; j++) {
#pragma unroll
        for (int off = 16; off > 0; off >>= 1)
            acc[j] += __shfl_xor_sync(0xffffffffu, acc[j], off);
    }
    if (lane < MD) xiout[row * MD + lane] = acc[lane] + bp[lane];
}

// ---------------------------------------------------------------------------
// Per-row: A = reshape(gf, 16x16); g = A A^T + 0.1 I; solve g y = -xi/(t+eps);
// out = y @ Wl + bl.   One warp per row, 8 rows per block.
// Direct SPD solve (Gaussian elimination, no pivoting) replaces linalg.inv.
// ---------------------------------------------------------------------------
__global__ __launch_bounds__(256)
void solve_out_kernel(const float* __restrict__ gf, const float* __restrict__ xi,
                      const float* __restrict__ t,
                      const float* __restrict__ Wl, const float* __restrict__ bl,
                      float* __restrict__ out)
{
    __shared__ float Am[8][MD][MD];
    __shared__ float G [8][MD][MD + 1];
    __shared__ float Y [8][MD];

    const int w = threadIdx.x >> 5, lane = threadIdx.x & 31;
    const size_t row = (size_t)blockIdx.x * 8 + w;

    // Load A (coalesced)
    const float* gfr = gf + row * HID;
    for (int k = lane; k < HID; k += 32) Am[w][k >> 4][k & 15] = gfr[k];
    if (lane < MD) {
        const float tv = t[row] + 1e-6f;
        Y[w][lane] = -xi[row * MD + lane] / tv;
    }
    __syncwarp();

    // g = A A^T + 0.1 I  (each lane computes 8 of the 256 entries)
    for (int p = lane; p < MD * MD; p += 32) {
        const int i = p >> 4, j = p & 15;
        float s = (i == j) ? 0.1f : 0.0f;
#pragma unroll
        for (int k = 0; k < MD; k++) s += Am[w][i][k] * Am[w][j][k];
        G[w][i][j] = s;
    }
    __syncwarp();

    // Forward elimination (SPD, no pivoting). Row-per-lane for rows i > k.
    for (int k = 0; k < MD; k++) {
        const float piv = G[w][k][k];
        const int i = k + 1 + lane;
        if (i < MD) {
            const float f = G[w][i][k] / piv;
            for (int c = k; c < MD; c++) G[w][i][c] -= f * G[w][k][c];
            Y[w][i] -= f * Y[w][k];
        }
        __syncwarp();
    }
    // Back substitution (tiny; lane 0)
    if (lane == 0) {
        for (int k = MD - 1; k >= 0; k--) {
            float s = Y[w][k];
            for (int c = k + 1; c < MD; c++) s -= G[w][k][c] * Y[w][c];
            Y[w][k] = s / G[w][k][k];
        }
    }
    __syncwarp();

    float yr[MD];
#pragma unroll
    for (int k = 0; k < MD; k++) yr[k] = Y[w][k];

    // out = y @ Wl + bl  (coalesced across lanes; Wl is 50KB -> L2-resident)
    float* orow = out + row * DD;
    for (int o = lane; o < DD; o += 32) {
        float s = __ldg(bl + o);
#pragma unroll
        for (int k = 0; k < MD; k++) s += yr[k] * __ldg(Wl + (size_t)k * DD + o);
        orow[o] = s;
    }
}

// ---------------------------------------------------------------------------
extern "C" void kernel_launch(void* const* d_in, const int* in_sizes, int n_in,
                              void* d_out, int out_size)
{
    const float* x_t = (const float*)d_in[0];
    const float* t   = (const float*)d_in[1];
    const float* W1  = (const float*)d_in[2];
    const float* b1  = (const float*)d_in[3];
    const float* W2  = (const float*)d_in[4];
    const float* b2  = (const float*)d_in[5];
    const float* Wp  = (const float*)d_in[6];
    const float* bp  = (const float*)d_in[7];
    const float* Wl  = (const float*)d_in[8];
    const float* bl  = (const float*)d_in[9];
    float* out = (float*)d_out;

    float *hptr, *gfptr, *xiptr;
    cudaGetSymbolAddress((void**)&hptr,  g_h);
    cudaGetSymbolAddress((void**)&gfptr, g_gf);
    cudaGetSymbolAddress((void**)&xiptr, g_xi);

    // xi = x @ Wp + bp
    xi_kernel<<<BATCH_ / 8, 256>>>(x_t, Wp, bp, xiptr);

    // h = relu(x @ W1 + b1)
    {
        dim3 grid(HID / 128, BATCH_ / 128);
        sgemm128<1><<<grid, 256>>>(x_t, W1, b1, hptr, BATCH_, HID, DD);
    }
    // gf = h @ W2 + b2
    {
        dim3 grid(HID / 128, BATCH_ / 128);
        sgemm128<0><<<grid, 256>>>(hptr, W2, b2, gfptr, BATCH_, HID, HID);
    }
    // build g, solve, project to data space
    solve_out_kernel<<<BATCH_ / 8, 256>>>(gfptr, xiptr, t, Wl, bl, out);
}

// round 4
// speedup vs baseline: 5.3554x; 5.3554x over previous
#include <cuda_runtime.h>
#include <cuda_fp16.h>

#define B_  131072
#define DD  784
#define HID 256
#define MD  16

// weights: [nb(2)][chunk][128 n][64 k halves, 16B-swizzled]
__device__ __align__(16) __half g_W1s_hi[2 * 13 * 8192];
__device__ __align__(16) __half g_W1s_lo[2 * 13 * 8192];
__device__ __align__(16) __half g_W2s_hi[2 * 4 * 8192];
__device__ __align__(16) __half g_W2s_lo[2 * 4 * 8192];
// h: [mb(B/64)][kchunk(4)][64 r][64 k halves, swizzled]
__device__ __align__(16) __half g_h_hi[(size_t)B_ * HID];
__device__ __align__(16) __half g_h_lo[(size_t)B_ * HID];
__device__ __align__(16) float g_gf[(size_t)B_ * HID];
__device__ __align__(16) float g_xi[(size_t)B_ * MD];

__device__ __forceinline__ unsigned su32(const void* p) {
    unsigned a;
    asm("{ .reg .u64 t; cvta.to.shared.u64 t, %1; cvt.u32.u64 %0, t; }" : "=r"(a) : "l"(p));
    return a;
}
__device__ __forceinline__ void ldm4(unsigned (&r)[4], unsigned addr) {
    asm volatile("ldmatrix.sync.aligned.m8n8.x4.shared.b16 {%0,%1,%2,%3}, [%4];"
                 : "=r"(r[0]), "=r"(r[1]), "=r"(r[2]), "=r"(r[3]) : "r"(addr));
}
__device__ __forceinline__ void mma16816(float (&c)[4], const unsigned (&a)[4],
                                         unsigned b0, unsigned b1) {
    asm volatile("mma.sync.aligned.m16n8k16.row.col.f32.f16.f16.f32 "
                 "{%0,%1,%2,%3}, {%4,%5,%6,%7}, {%8,%9}, {%0,%1,%2,%3};"
                 : "+f"(c[0]), "+f"(c[1]), "+f"(c[2]), "+f"(c[3])
                 : "r"(a[0]), "r"(a[1]), "r"(a[2]), "r"(a[3]), "r"(b0), "r"(b1));
}
__device__ __forceinline__ void cpa16(unsigned s, const void* g) {
    asm volatile("cp.async.cg.shared.global [%0], [%1], 16;" :: "r"(s), "l"(g));
}
#define CP_COMMIT() asm volatile("cp.async.commit_group;" ::: "memory")
#define CP_WAIT0()  asm volatile("cp.async.wait_group 0;" ::: "memory")

__device__ __forceinline__ unsigned pk(__half a, __half b) {
    return (unsigned)__half_as_ushort(a) | ((unsigned)__half_as_ushort(b) << 16);
}
__device__ __forceinline__ void split(float v, __half& h, __half& l) {
    h = __float2half_rn(v);
    l = __float2half_rn(v - __half2float(h));
}

// smem layout (bytes): A hi: s*8192 ; A lo: 16384+s*8192 ; B hi: 32768+s*16384 ; B lo: 65536+s*16384
#define ASH(s) ((s) * 8192)
#define BSH(s) (32768 + (s) * 16384)
#define SMEMB  98304

// prep: W^T, fp16 hi/lo split, zero-pad K, pre-swizzle
__global__ void prep_kernel(const float* __restrict__ W1, const float* __restrict__ W2) {
    int idx = blockIdx.x * 256 + threadIdx.x;
    const int T1 = 2 * 13 * 8192;
    if (idx < T1) {
        int nb = idx / (13 * 8192), rem = idx % (13 * 8192);
        int c = rem >> 13, p = rem & 8191, n = p >> 6, k = p & 63;
        int kg = c * 64 + k;
        float v = (kg < DD) ? W1[(size_t)kg * HID + nb * 128 + n] : 0.0f;
        __half h, l; split(v, h, l);
        int dst = idx - p + n * 64 + (((k >> 3) ^ (n & 7)) << 3) + (k & 7);
        g_W1s_hi[dst] = h; g_W1s_lo[dst] = l;
    } else if (idx < T1 + 2 * 4 * 8192) {
        int u = idx - T1;
        int nb = u / (4 * 8192), rem = u % (4 * 8192);
        int c = rem >> 13, p = rem & 8191, n = p >> 6, k = p & 63;
        int kg = c * 64 + k;
        float v = W2[(size_t)kg * HID + nb * 128 + n];
        __half h, l; split(v, h, l);
        int dst = u - p + n * 64 + (((k >> 3) ^ (n & 7)) << 3) + (k & 7);
        g_W2s_hi[dst] = h; g_W2s_lo[dst] = l;
    }
}

// MODE=1: A = fp32 X split in-kernel; out = relu -> fp16 hi/lo tiled (g_h_*)
// MODE=0: A = tiled fp16 hi/lo (g_h_*); out = fp32 row-major (g_gf)
template <int CHUNKS, int MODE>
__global__ __launch_bounds__(256, 2)
void gemm_mma(const float* __restrict__ X, const float* __restrict__ bias,
              const __half* __restrict__ Bh, const __half* __restrict__ Bl)
{
    extern __shared__ char smc[];
    const unsigned sb = su32(smc);
    const int tid = threadIdx.x, lane = tid & 31, w = tid >> 5;
    const int wm = w >> 2, wn = w & 3;
    const int mb = blockIdx.x, nb = blockIdx.y;

    float acc[2][4][4] = {};
    float4 xv[4];

    const int ar = tid >> 2, uo = (tid & 3) * 2;   // MODE1 A staging coords
    const int t8 = lane >> 3, r8 = lane & 7;

    auto ldgA1 = [&](int c) {
#pragma unroll
        for (int q = 0; q < 4; q++) {
            int col = c * 64 + uo * 8 + q * 4;
            xv[q] = (col < DD) ? *(const float4*)(X + ((size_t)mb * 64 + ar) * DD + col)
                               : make_float4(0.f, 0.f, 0.f, 0.f);
        }
    };
    auto stsA1 = [&](int s) {
        __half h[16], l[16];
        const float* f = (const float*)xv;
#pragma unroll
        for (int i = 0; i < 16; i++) split(f[i], h[i], l[i]);
#pragma unroll
        for (int u = 0; u < 2; u++) {
            uint4 vh, vl;
            vh.x = pk(h[u*8+0], h[u*8+1]); vh.y = pk(h[u*8+2], h[u*8+3]);
            vh.z = pk(h[u*8+4], h[u*8+5]); vh.w = pk(h[u*8+6], h[u*8+7]);
            vl.x = pk(l[u*8+0], l[u*8+1]); vl.y = pk(l[u*8+2], l[u*8+3]);
            vl.z = pk(l[u*8+4], l[u*8+5]); vl.w = pk(l[u*8+6], l[u*8+7]);
            unsigned o = ar * 128 + (((uo + u) ^ (ar & 7)) << 4);
            *(uint4*)(smc + ASH(s) + o) = vh;
            *(uint4*)(smc + ASH(s) + 16384 + o) = vl;
        }
    };
    auto cpaA0 = [&](int c, int s) {   // MODE0: A tiles via cp.async
#pragma unroll
        for (int i = 0; i < 2; i++) {
            int j = tid * 2 + i;
            cpa16(sb + ASH(s) + j * 16,         g_h_hi + ((size_t)mb * 4 + c) * 4096 + j * 8);
            cpa16(sb + ASH(s) + 16384 + j * 16, g_h_lo + ((size_t)mb * 4 + c) * 4096 + j * 8);
        }
    };
    auto cpaB = [&](int c, int s) {
        const size_t o = ((size_t)nb * CHUNKS + c) * 8192;
#pragma unroll
        for (int i = 0; i < 4; i++) {
            int j = tid + i * 256;
            cpa16(sb + BSH(s) + j * 16,         Bh + o + j * 8);
            cpa16(sb + BSH(s) + 32768 + j * 16, Bl + o + j * 8);
        }
    };

    // preload chunk 0
    if (MODE == 1) { ldgA1(0); stsA1(0); } else cpaA0(0, 0);
    cpaB(0, 0);
    CP_COMMIT(); CP_WAIT0();
    __syncthreads();

    for (int c = 0; c < CHUNKS; c++) {
        const int s = c & 1;
        const bool more = (c + 1 < CHUNKS);
        if (more) {
            if (MODE == 1) ldgA1(c + 1); else cpaA0(c + 1, s ^ 1);
            cpaB(c + 1, s ^ 1);
            CP_COMMIT();
        }
#pragma unroll
        for (int kk = 0; kk < 4; kk++) {
            unsigned ah[2][4], al[2][4], bhf[2][4], blf[2][4];
#pragma unroll
            for (int mi = 0; mi < 2; mi++) {
                int m = wm * 32 + mi * 16 + (t8 & 1) * 8 + r8;
                int u = kk * 2 + (t8 >> 1);
                unsigned ad = sb + ASH(s) + m * 128 + ((u ^ (m & 7)) << 4);
                ldm4(ah[mi], ad);
                ldm4(al[mi], ad + 16384);
            }
#pragma unroll
            for (int ng = 0; ng < 2; ng++) {
                int n = wn * 32 + ng * 16 + (t8 & 1) * 8 + r8;
                int u = kk * 2 + (t8 >> 1);
                unsigned bd = sb + BSH(s) + n * 128 + ((u ^ (n & 7)) << 4);
                ldm4(bhf[ng], bd);
                ldm4(blf[ng], bd + 32768);
            }
#pragma unroll
            for (int mi = 0; mi < 2; mi++)
#pragma unroll
                for (int nj = 0; nj < 4; nj++) {
                    const int g = nj >> 1, o = nj & 1;
                    mma16816(acc[mi][nj], ah[mi], bhf[g][o], bhf[g][o + 2]);
                    mma16816(acc[mi][nj], ah[mi], blf[g][o], blf[g][o + 2]);
                    mma16816(acc[mi][nj], al[mi], bhf[g][o], bhf[g][o + 2]);
                }
        }
        if (more && MODE == 1) stsA1(s ^ 1);
        CP_WAIT0();
        __syncthreads();
    }

    // epilogue
    const int rq = lane >> 2, cq = (lane & 3) * 2;
#pragma unroll
    for (int mi = 0; mi < 2; mi++)
#pragma unroll
        for (int nj = 0; nj < 4; nj++) {
            const int ng = nb * 128 + wn * 32 + nj * 8 + cq;   // global out col
            const float bb0 = __ldg(bias + ng), bb1 = __ldg(bias + ng + 1);
#pragma unroll
            for (int hr = 0; hr < 2; hr++) {
                const int r = wm * 32 + mi * 16 + rq + hr * 8;
                float v0 = acc[mi][nj][hr * 2 + 0] + bb0;
                float v1 = acc[mi][nj][hr * 2 + 1] + bb1;
                if (MODE == 1) {
                    v0 = fmaxf(v0, 0.0f); v1 = fmaxf(v1, 0.0f);
                    __half h0, l0, h1, l1;
                    split(v0, h0, l0); split(v1, h1, l1);
                    const int kc2 = ng >> 6, q = ng & 63;
                    const size_t base = (((size_t)mb * 4 + kc2) * 64 + r) * 64 +
                                        (((q >> 3) ^ (r & 7)) << 3) + (q & 7);
                    *(unsigned*)(g_h_hi + base) = pk(h0, h1);
                    *(unsigned*)(g_h_lo + base) = pk(l0, l1);
                } else {
                    float2 v = make_float2(v0, v1);
                    *(float2*)(g_gf + ((size_t)mb * 64 + r) * HID + ng) = v;
                }
            }
        }
}

// xi = x @ Wp + bp, Wp transposed into smem
__global__ __launch_bounds__(256)
void xi_kernel(const float* __restrict__ x, const float* __restrict__ Wp,
               const float* __restrict__ bp, float* __restrict__ xo)
{
    extern __shared__ float Wps[];  // [16][784]
    for (int i = threadIdx.x; i < DD * MD; i += 256) {
        int k = i >> 4, j = i & 15;
        Wps[j * DD + k] = Wp[i];
    }
    __syncthreads();
    const int w = threadIdx.x >> 5, lane = threadIdx.x & 31;
    for (int it = 0; it < 8; it++) {
        size_t row = (size_t)blockIdx.x * 64 + it * 8 + w;
        const float* xr = x + row * DD;
        float acc[MD];
#pragma unroll
        for (int j = 0; j < MD; j++) acc[j] = 0.0f;
        for (int k = lane; k < DD; k += 32) {
            float xvv = xr[k];
#pragma unroll
            for (int j = 0; j < MD; j++) acc[j] += xvv * Wps[j * DD + k];
        }
#pragma unroll
        for (int j = 0; j < MD; j++)
#pragma unroll
            for (int off = 16; off > 0; off >>= 1)
                acc[j] += __shfl_xor_sync(0xffffffffu, acc[j], off);
        if (lane < MD) xo[row * MD + lane] = acc[lane] + bp[lane];
    }
}

// per-row SPD solve + cooperative Wl epilogue (8 rows/block)
__global__ __launch_bounds__(256)
void solve_out_kernel(const float* __restrict__ gf, const float* __restrict__ xi,
                      const float* __restrict__ t,
                      const float* __restrict__ Wl, const float* __restrict__ bl,
                      float* __restrict__ out)
{
    __shared__ float Am[8][MD][MD];
    __shared__ float G[8][MD][MD + 1];
    __shared__ float Ys[8][MD];
    const int w = threadIdx.x >> 5, lane = threadIdx.x & 31;
    const size_t row = (size_t)blockIdx.x * 8 + w;

    const float* gfr = gf + row * HID;
    for (int k = lane; k < HID; k += 32) Am[w][k >> 4][k & 15] = gfr[k];
    if (lane < MD) Ys[w][lane] = -xi[row * MD + lane] / (t[row] + 1e-6f);
    __syncwarp();
    for (int p = lane; p < MD * MD; p += 32) {
        const int i = p >> 4, j = p & 15;
        float s = (i == j) ? 0.1f : 0.0f;
#pragma unroll
        for (int k = 0; k < MD; k++) s += Am[w][i][k] * Am[w][j][k];
        G[w][i][j] = s;
    }
    __syncwarp();
    for (int k = 0; k < MD; k++) {
        const float piv = G[w][k][k];
        const int i = k + 1 + lane;
        if (i < MD) {
            const float f = G[w][i][k] / piv;
            for (int c = k; c < MD; c++) G[w][i][c] -= f * G[w][k][c];
            Ys[w][i] -= f * Ys[w][k];
        }
        __syncwarp();
    }
    if (lane == 0) {
        for (int k = MD - 1; k >= 0; k--) {
            float s = Ys[w][k];
            for (int c = k + 1; c < MD; c++) s -= G[w][k][c] * Ys[w][c];
            Ys[w][k] = s / G[w][k][k];
        }
    }
    __syncthreads();

    const size_t rbase = (size_t)blockIdx.x * 8;
    for (int col = threadIdx.x; col < DD; col += 256) {
        float wv[MD];
#pragma unroll
        for (int k = 0; k < MD; k++) wv[k] = __ldg(Wl + (size_t)k * DD + col);
        const float base = __ldg(bl + col);
#pragma unroll
        for (int r = 0; r < 8; r++) {
            float s = base;
#pragma unroll
            for (int k = 0; k < MD; k++) s += Ys[r][k] * wv[k];
            out[(rbase + r) * DD + col] = s;
        }
    }
}

extern "C" void kernel_launch(void* const* d_in, const int* in_sizes, int n_in,
                              void* d_out, int out_size)
{
    const float* x_t = (const float*)d_in[0];
    const float* t   = (const float*)d_in[1];
    const float* W1  = (const float*)d_in[2];
    const float* b1  = (const float*)d_in[3];
    const float* W2  = (const float*)d_in[4];
    const float* b2  = (const float*)d_in[5];
    const float* Wp  = (const float*)d_in[6];
    const float* bp  = (const float*)d_in[7];
    const float* Wl  = (const float*)d_in[8];
    const float* bl  = (const float*)d_in[9];
    float* out = (float*)d_out;

    cudaFuncSetAttribute((const void*)gemm_mma<13, 1>, cudaFuncAttributeMaxDynamicSharedMemorySize, SMEMB);
    cudaFuncSetAttribute((const void*)gemm_mma<4, 0>,  cudaFuncAttributeMaxDynamicSharedMemorySize, SMEMB);
    cudaFuncSetAttribute((const void*)xi_kernel, cudaFuncAttributeMaxDynamicSharedMemorySize, DD * MD * 4);

    __half *w1h, *w1l, *w2h, *w2l;
    float *gfp, *xip;
    cudaGetSymbolAddress((void**)&w1h, g_W1s_hi);
    cudaGetSymbolAddress((void**)&w1l, g_W1s_lo);
    cudaGetSymbolAddress((void**)&w2h, g_W2s_hi);
    cudaGetSymbolAddress((void**)&w2l, g_W2s_lo);
    cudaGetSymbolAddress((void**)&gfp, g_gf);
    cudaGetSymbolAddress((void**)&xip, g_xi);

    prep_kernel<<<1088, 256>>>(W1, W2);
    xi_kernel<<<B_ / 64, 256, DD * MD * 4>>>(x_t, Wp, bp, xip);
    gemm_mma<13, 1><<<dim3(B_ / 64, 2), 256, SMEMB>>>(x_t, b1, w1h, w1l);
    gemm_mma<4, 0><<<dim3(B_ / 64, 2), 256, SMEMB>>>(nullptr, b2, w2h, w2l);
    solve_out_kernel<<<B_ / 8, 256>>>(gfp, xip, t, Wl, bl, out);
}